// round 2
// baseline (speedup 1.0000x reference)
#include <cuda_runtime.h>
#include <cstdint>
#include <cstdio>

// Problem constants (from reference)
#define NMAX   100000
#define INF    128
#define HID    64
#define OUTF   40

// ---------------- scratch (device globals; no allocation allowed) ----------
__device__ float g_deg [NMAX];
__device__ float g_dinv[NMAX];
__device__ float g_h0  [(size_t)NMAX * HID];   // x @ W1
__device__ float g_h1  [(size_t)NMAX * HID];   // aggregated conv1 (pre-bias, pre-relu)
__device__ float g_t   [(size_t)NMAX * HID];   // relu(h1+b1) @ W2
__device__ float g_emb [(size_t)NMAX * HID];   // aggregated conv2 (pre-bias)
__device__ int   g_idx64;                      // 1 if edge_index is int64

// ---------------- edge index dtype sniffing --------------------------------
// int64 nonneg values < 2^31 -> every odd 32-bit word is 0.
// int32 -> odd words are edge indices (random in [0,1e5)): ~surely nonzero.
__global__ void k_detect(const unsigned int* __restrict__ w) {
    int t = threadIdx.x;
    int nz = 0;
#pragma unroll
    for (int i = 0; i < 8; i++) {
        nz |= (w[2 * (t * 8 + i) + 1] != 0u);
    }
    int any = __syncthreads_or(nz);
    if (t == 0) g_idx64 = (any == 0) ? 1 : 0;
}

__device__ __forceinline__ void load_edge(const void* eidx, int E, int e, int& s, int& d) {
    if (g_idx64) {
        const long long* p = (const long long*)eidx;
        s = (int)p[e];
        d = (int)p[(size_t)E + e];
    } else {
        const int* p = (const int*)eidx;
        s = p[e];
        d = p[(size_t)E + e];
    }
}

// ---------------- degree / norm --------------------------------------------
__global__ void k_deg_init(int n) {
    int i = blockIdx.x * blockDim.x + threadIdx.x;
    if (i < n) g_deg[i] = 1.0f;   // self-loop
}

__global__ void k_deg(const void* __restrict__ eidx, int E) {
    int e = blockIdx.x * blockDim.x + threadIdx.x;
    if (e >= E) return;
    int s, d;
    load_edge(eidx, E, e, s, d);
    atomicAdd(&g_deg[d], 1.0f);
}

__global__ void k_dinv(int n) {
    int i = blockIdx.x * blockDim.x + threadIdx.x;
    if (i < n) g_dinv[i] = rsqrtf(g_deg[i]);
}

// ---------------- GEMM: [n,KDIM] @ [KDIM,64] -> C, plus self-init ----------
// BM=64, BN=64, BK=16, 256 threads, 4x4 microtile.
// If ACT: input element a -> relu(a + actb[k]) (used for conv2 input).
// Epilogue also writes Cself = C * dinv[row]^2 (self-loop contribution),
// which is the init value for the subsequent edge scatter-add.
template <int KDIM, bool ACT>
__global__ void k_gemm64(const float* __restrict__ A, const float* __restrict__ W,
                         const float* __restrict__ actb,
                         float* __restrict__ C, float* __restrict__ Cself, int n) {
    __shared__ float xs[16][68];   // [k][m], padded
    __shared__ float ws[16][64];   // [k][c]
    const int tid = threadIdx.x;
    const int tx = tid & 15;       // col group (4 cols)
    const int ty = tid >> 4;       // row group (4 rows)
    const int rowBase = blockIdx.x * 64;

    float acc[4][4];
#pragma unroll
    for (int i = 0; i < 4; i++)
#pragma unroll
        for (int j = 0; j < 4; j++) acc[i][j] = 0.f;

    for (int k0 = 0; k0 < KDIM; k0 += 16) {
        // load A tile (64 rows x 16 k), transposed into xs[k][m]
        {
            int i  = tid * 4;
            int m  = i >> 4;
            int kk = i & 15;
            int row = rowBase + m;
            float4 v = make_float4(0.f, 0.f, 0.f, 0.f);
            if (row < n) {
                v = *(const float4*)&A[(size_t)row * KDIM + k0 + kk];
                if (ACT) {
                    v.x = fmaxf(v.x + actb[k0 + kk + 0], 0.f);
                    v.y = fmaxf(v.y + actb[k0 + kk + 1], 0.f);
                    v.z = fmaxf(v.z + actb[k0 + kk + 2], 0.f);
                    v.w = fmaxf(v.w + actb[k0 + kk + 3], 0.f);
                }
            }
            xs[kk + 0][m] = v.x;
            xs[kk + 1][m] = v.y;
            xs[kk + 2][m] = v.z;
            xs[kk + 3][m] = v.w;
        }
        // load W tile (16 k x 64 c)
        {
            int i  = tid * 4;
            int kk = i >> 6;
            int c  = i & 63;
            *(float4*)&ws[kk][c] = *(const float4*)&W[(size_t)(k0 + kk) * 64 + c];
        }
        __syncthreads();
#pragma unroll
        for (int k = 0; k < 16; k++) {
            float4 a = *(const float4*)&xs[k][ty * 4];
            float4 b = *(const float4*)&ws[k][tx * 4];
            float av[4] = {a.x, a.y, a.z, a.w};
            float bv[4] = {b.x, b.y, b.z, b.w};
#pragma unroll
            for (int i = 0; i < 4; i++)
#pragma unroll
                for (int j = 0; j < 4; j++) acc[i][j] += av[i] * bv[j];
        }
        __syncthreads();
    }

#pragma unroll
    for (int i = 0; i < 4; i++) {
        int row = rowBase + ty * 4 + i;
        if (row < n) {
            float4 v = make_float4(acc[i][0], acc[i][1], acc[i][2], acc[i][3]);
            *(float4*)&C[(size_t)row * 64 + tx * 4] = v;
            float di = g_dinv[row];
            float w  = di * di;
            float4 u = make_float4(v.x * w, v.y * w, v.z * w, v.w * w);
            *(float4*)&Cself[(size_t)row * 64 + tx * 4] = u;
        }
    }
}

// ---------------- edge scatter: dst += src_feat[src] * dinv[s]*dinv[d] -----
// one warp per edge; lane handles 2 consecutive features via float2 gather.
__global__ void k_scatter(const void* __restrict__ eidx, int E,
                          const float* __restrict__ src_feat,
                          float* __restrict__ dst_feat) {
    int gw   = (blockIdx.x * blockDim.x + threadIdx.x) >> 5;
    int lane = threadIdx.x & 31;
    if (gw >= E) return;
    int s, d;
    load_edge(eidx, E, gw, s, d);
    float w = g_dinv[s] * g_dinv[d];
    float2 v = ((const float2*)src_feat)[(size_t)s * 32 + lane];
    float* p = &dst_feat[(size_t)d * 64 + 2 * lane];
    atomicAdd(p + 0, v.x * w);
    atomicAdd(p + 1, v.y * w);
}

// ---------------- final head: emb+b2, logits, softmax, argmax --------------
// one block (256 threads) per 64 nodes.
__global__ void k_final(const float* __restrict__ Wc, const float* __restrict__ bc,
                        const float* __restrict__ b2,
                        float* __restrict__ out, int n) {
    __shared__ float Wcs[64][40];
    __shared__ float embs[64][65];
    __shared__ float lg[64][41];
    __shared__ float bcs[40];
    __shared__ float b2s[64];
    __shared__ float rsum[64];

    int tid  = threadIdx.x;
    int base = blockIdx.x * 64;

    for (int i = tid; i < 64 * 40; i += 256) Wcs[i / 40][i % 40] = Wc[i];
    if (tid < 40) bcs[tid] = bc[tid];
    if (tid < 64) b2s[tid] = b2[tid];
    __syncthreads();

    float* outL = out;
    float* outE = out + (size_t)n * 40;
    float* outS = out + (size_t)n * 104;
    float* outH = out + (size_t)n * 144;

    // stage emb (+b2) into smem, write embedding output coalesced
    for (int i = tid; i < 64 * 64; i += 256) {
        int r = i >> 6, c = i & 63;
        int node = base + r;
        float v = 0.f;
        if (node < n) {
            v = g_emb[(size_t)node * 64 + c] + b2s[c];
            outE[(size_t)node * 64 + c] = v;
        }
        embs[r][c] = v;
    }
    __syncthreads();

    // logits: 64x40 = 2560 outputs; thread (ty,tx) computes 2 rows x 5 cols
    int tx = tid & 7, ty = tid >> 3;
    float acc[2][5];
#pragma unroll
    for (int i = 0; i < 2; i++)
#pragma unroll
        for (int j = 0; j < 5; j++) acc[i][j] = bcs[tx * 5 + j];
    for (int k = 0; k < 64; k++) {
        float a0 = embs[ty * 2 + 0][k];
        float a1 = embs[ty * 2 + 1][k];
#pragma unroll
        for (int j = 0; j < 5; j++) {
            float b = Wcs[k][tx * 5 + j];
            acc[0][j] += a0 * b;
            acc[1][j] += a1 * b;
        }
    }
#pragma unroll
    for (int i = 0; i < 2; i++)
#pragma unroll
        for (int j = 0; j < 5; j++) lg[ty * 2 + i][tx * 5 + j] = acc[i][j];
    __syncthreads();

    // write logits coalesced
    for (int i = tid; i < 64 * 40; i += 256) {
        int r = i / 40, c = i % 40;
        int node = base + r;
        if (node < n) outL[(size_t)node * 40 + c] = lg[r][c];
    }
    __syncthreads();

    // per-node softmax stats; overwrite lg rows with exp values
    if (tid < 64) {
        int node = base + tid;
        float m = -1e30f;
        int bi = 0;
#pragma unroll
        for (int j = 0; j < 40; j++) {
            float v = lg[tid][j];
            if (v > m) { m = v; bi = j; }
        }
        float s = 0.f;
#pragma unroll
        for (int j = 0; j < 40; j++) {
            float e = __expf(lg[tid][j] - m);
            lg[tid][j] = e;
            s += e;
        }
        rsum[tid] = 1.f / s;
        if (node < n) outH[node] = (float)bi;
    }
    __syncthreads();

    // write softmax coalesced
    for (int i = tid; i < 64 * 40; i += 256) {
        int r = i / 40, c = i % 40;
        int node = base + r;
        if (node < n) outS[(size_t)node * 40 + c] = lg[r][c] * rsum[r];
    }
}

// ---------------- launch ----------------------------------------------------
extern "C" void kernel_launch(void* const* d_in, const int* in_sizes, int n_in,
                              void* d_out, int out_size) {
    const float* x  = (const float*)d_in[0];
    const void*  ei = d_in[1];
    const float* W1 = (const float*)d_in[2];
    const float* b1 = (const float*)d_in[3];
    const float* W2 = (const float*)d_in[4];
    const float* b2 = (const float*)d_in[5];
    const float* Wc = (const float*)d_in[6];
    const float* bc = (const float*)d_in[7];
    float* out = (float*)d_out;

    int n = in_sizes[0] / INF;   // nodes
    int E = in_sizes[1] / 2;     // edges

    // scratch pointers (every call; no caching)
    float *ph0, *ph1, *pt, *pemb;
    cudaGetSymbolAddress((void**)&ph0,  g_h0);
    cudaGetSymbolAddress((void**)&ph1,  g_h1);
    cudaGetSymbolAddress((void**)&pt,   g_t);
    cudaGetSymbolAddress((void**)&pemb, g_emb);

    int nb256  = (n + 255) / 256;
    int eb256  = (E + 255) / 256;
    int gBlk   = (n + 63) / 64;
    int sBlk   = (E + 7) / 8;   // warp per edge, 8 warps/block

    k_detect<<<1, 256>>>((const unsigned int*)ei);
    k_deg_init<<<nb256, 256>>>(n);
    k_deg<<<eb256, 256>>>(ei, E);
    k_dinv<<<nb256, 256>>>(n);

    // conv1: h0 = x@W1 ; h1 init = h0 * dinv^2 (self-loop)
    k_gemm64<INF, false><<<gBlk, 256>>>(x, W1, nullptr, ph0, ph1, n);
    k_scatter<<<sBlk, 256>>>(ei, E, ph0, ph1);

    // conv2: t = relu(h1+b1)@W2 ; emb init = t * dinv^2
    k_gemm64<HID, true><<<gBlk, 256>>>(ph1, W2, b1, pt, pemb, n);
    k_scatter<<<sBlk, 256>>>(ei, E, pt, pemb);

    // head: emb+b2, logits, softmax, argmax
    k_final<<<gBlk, 256>>>(Wc, bc, b2, out, n);
}

// round 3
// speedup vs baseline: 1.4266x; 1.4266x over previous
#include <cuda_runtime.h>
#include <cstdint>
#include <cstdio>

// Problem constants (from reference)
#define NMAX   100000
#define INF    128
#define HID    64
#define OUTF   40

// ---------------- scratch (device globals; no allocation allowed) ----------
__device__ float g_deg [NMAX];
__device__ float g_dinv[NMAX];
__device__ float g_h0  [(size_t)NMAX * HID];   // x @ W1
__device__ float g_h1  [(size_t)NMAX * HID];   // aggregated conv1 (pre-bias, pre-relu)
__device__ float g_t   [(size_t)NMAX * HID];   // relu(h1+b1) @ W2
__device__ float g_emb [(size_t)NMAX * HID];   // aggregated conv2 (pre-bias)
__device__ int   g_idx64;                      // 1 if edge_index is int64

// ---------------- edge index dtype sniffing --------------------------------
__global__ void k_detect(const unsigned int* __restrict__ w) {
    int t = threadIdx.x;
    int nz = 0;
#pragma unroll
    for (int i = 0; i < 8; i++) {
        nz |= (w[2 * (t * 8 + i) + 1] != 0u);
    }
    int any = __syncthreads_or(nz);
    if (t == 0) g_idx64 = (any == 0) ? 1 : 0;
}

__device__ __forceinline__ void load_edge(const void* eidx, int E, int e, int& s, int& d) {
    if (g_idx64) {
        const long long* p = (const long long*)eidx;
        s = (int)p[e];
        d = (int)p[(size_t)E + e];
    } else {
        const int* p = (const int*)eidx;
        s = p[e];
        d = p[(size_t)E + e];
    }
}

// ---------------- degree / norm --------------------------------------------
__global__ void k_deg_init(int n) {
    int i = blockIdx.x * blockDim.x + threadIdx.x;
    if (i < n) g_deg[i] = 1.0f;   // self-loop
}

__global__ void k_deg(const void* __restrict__ eidx, int E) {
    int e = blockIdx.x * blockDim.x + threadIdx.x;
    if (e >= E) return;
    int s, d;
    load_edge(eidx, E, e, s, d);
    atomicAdd(&g_deg[d], 1.0f);
}

__global__ void k_dinv(int n) {
    int i = blockIdx.x * blockDim.x + threadIdx.x;
    if (i < n) g_dinv[i] = rsqrtf(g_deg[i]);
}

// ---------------- GEMM: [n,KDIM] @ [KDIM,64] -> C, plus self-init ----------
// BM=128, BN=64, BK=16, 256 threads, 8x4 microtile.
// If ACT: input element a -> relu(a + actb[k]).
// Epilogue also writes Cself = C * dinv[row]^2 (self-loop init for scatter).
template <int KDIM, bool ACT>
__global__ void k_gemm64(const float* __restrict__ A, const float* __restrict__ W,
                         const float* __restrict__ actb,
                         float* __restrict__ C, float* __restrict__ Cself, int n) {
    __shared__ float xs[16][132];  // [k][m], padded
    __shared__ float ws[16][64];   // [k][c]
    const int tid = threadIdx.x;
    const int tx = tid & 15;       // col group (4 cols)
    const int ty = tid >> 4;       // row group (8 rows), 0..15
    const int rowBase = blockIdx.x * 128;

    float acc[8][4];
#pragma unroll
    for (int i = 0; i < 8; i++)
#pragma unroll
        for (int j = 0; j < 4; j++) acc[i][j] = 0.f;

    for (int k0 = 0; k0 < KDIM; k0 += 16) {
        // load A tile (128 rows x 16 k), transposed into xs[k][m]
#pragma unroll
        for (int half = 0; half < 2; half++) {
            int i  = tid * 4;
            int m  = (i >> 4) + half * 64;
            int kk = i & 15;
            int row = rowBase + m;
            float4 v = make_float4(0.f, 0.f, 0.f, 0.f);
            if (row < n) {
                v = *(const float4*)&A[(size_t)row * KDIM + k0 + kk];
                if (ACT) {
                    v.x = fmaxf(v.x + actb[k0 + kk + 0], 0.f);
                    v.y = fmaxf(v.y + actb[k0 + kk + 1], 0.f);
                    v.z = fmaxf(v.z + actb[k0 + kk + 2], 0.f);
                    v.w = fmaxf(v.w + actb[k0 + kk + 3], 0.f);
                }
            }
            xs[kk + 0][m] = v.x;
            xs[kk + 1][m] = v.y;
            xs[kk + 2][m] = v.z;
            xs[kk + 3][m] = v.w;
        }
        // load W tile (16 k x 64 c)
        {
            int i  = tid * 4;
            int kk = i >> 6;
            int c  = i & 63;
            *(float4*)&ws[kk][c] = *(const float4*)&W[(size_t)(k0 + kk) * 64 + c];
        }
        __syncthreads();
#pragma unroll
        for (int k = 0; k < 16; k++) {
            float4 b  = *(const float4*)&ws[k][tx * 4];
            float4 a0 = *(const float4*)&xs[k][ty * 8];
            float4 a1 = *(const float4*)&xs[k][ty * 8 + 4];
            float av[8] = {a0.x, a0.y, a0.z, a0.w, a1.x, a1.y, a1.z, a1.w};
            float bv[4] = {b.x, b.y, b.z, b.w};
#pragma unroll
            for (int i = 0; i < 8; i++)
#pragma unroll
                for (int j = 0; j < 4; j++) acc[i][j] += av[i] * bv[j];
        }
        __syncthreads();
    }

#pragma unroll
    for (int i = 0; i < 8; i++) {
        int row = rowBase + ty * 8 + i;
        if (row < n) {
            float4 v = make_float4(acc[i][0], acc[i][1], acc[i][2], acc[i][3]);
            *(float4*)&C[(size_t)row * 64 + tx * 4] = v;
            float di = g_dinv[row];
            float w  = di * di;
            float4 u = make_float4(v.x * w, v.y * w, v.z * w, v.w * w);
            *(float4*)&Cself[(size_t)row * 64 + tx * 4] = u;
        }
    }
}

// ---------------- edge scatter: dst += src_feat[src] * dinv[s]*dinv[d] -----
// 16 lanes per edge; each lane gathers one float4 and issues ONE v4 RED.
__global__ void k_scatter(const void* __restrict__ eidx, int E,
                          const float* __restrict__ src_feat,
                          float* __restrict__ dst_feat) {
    int t    = blockIdx.x * blockDim.x + threadIdx.x;
    int e    = t >> 4;
    int lane = t & 15;
    if (e >= E) return;
    int s, d;
    load_edge(eidx, E, e, s, d);
    float w = g_dinv[s] * g_dinv[d];
    float4 v = ((const float4*)src_feat)[(size_t)s * 16 + lane];
    float* p = &dst_feat[(size_t)d * 64 + lane * 4];
    asm volatile("red.global.add.v4.f32 [%0], {%1,%2,%3,%4};"
                 :: "l"(p), "f"(v.x * w), "f"(v.y * w), "f"(v.z * w), "f"(v.w * w)
                 : "memory");
}

// ---------------- final head: emb+b2, logits, softmax, argmax --------------
__global__ void k_final(const float* __restrict__ Wc, const float* __restrict__ bc,
                        const float* __restrict__ b2,
                        float* __restrict__ out, int n) {
    __shared__ float Wcs[64][40];
    __shared__ float embs[64][65];
    __shared__ float lg[64][41];
    __shared__ float bcs[40];
    __shared__ float b2s[64];
    __shared__ float rsum[64];

    int tid  = threadIdx.x;
    int base = blockIdx.x * 64;

    for (int i = tid; i < 64 * 40; i += 256) Wcs[i / 40][i % 40] = Wc[i];
    if (tid < 40) bcs[tid] = bc[tid];
    if (tid < 64) b2s[tid] = b2[tid];
    __syncthreads();

    float* outL = out;
    float* outE = out + (size_t)n * 40;
    float* outS = out + (size_t)n * 104;
    float* outH = out + (size_t)n * 144;

    for (int i = tid; i < 64 * 64; i += 256) {
        int r = i >> 6, c = i & 63;
        int node = base + r;
        float v = 0.f;
        if (node < n) {
            v = g_emb[(size_t)node * 64 + c] + b2s[c];
            outE[(size_t)node * 64 + c] = v;
        }
        embs[r][c] = v;
    }
    __syncthreads();

    int tx = tid & 7, ty = tid >> 3;
    float acc[2][5];
#pragma unroll
    for (int i = 0; i < 2; i++)
#pragma unroll
        for (int j = 0; j < 5; j++) acc[i][j] = bcs[tx * 5 + j];
    for (int k = 0; k < 64; k++) {
        float a0 = embs[ty * 2 + 0][k];
        float a1 = embs[ty * 2 + 1][k];
#pragma unroll
        for (int j = 0; j < 5; j++) {
            float b = Wcs[k][tx * 5 + j];
            acc[0][j] += a0 * b;
            acc[1][j] += a1 * b;
        }
    }
#pragma unroll
    for (int i = 0; i < 2; i++)
#pragma unroll
        for (int j = 0; j < 5; j++) lg[ty * 2 + i][tx * 5 + j] = acc[i][j];
    __syncthreads();

    for (int i = tid; i < 64 * 40; i += 256) {
        int r = i / 40, c = i % 40;
        int node = base + r;
        if (node < n) outL[(size_t)node * 40 + c] = lg[r][c];
    }
    __syncthreads();

    if (tid < 64) {
        int node = base + tid;
        float m = -1e30f;
        int bi = 0;
#pragma unroll
        for (int j = 0; j < 40; j++) {
            float v = lg[tid][j];
            if (v > m) { m = v; bi = j; }
        }
        float s = 0.f;
#pragma unroll
        for (int j = 0; j < 40; j++) {
            float e = __expf(lg[tid][j] - m);
            lg[tid][j] = e;
            s += e;
        }
        rsum[tid] = 1.f / s;
        if (node < n) outH[node] = (float)bi;
    }
    __syncthreads();

    for (int i = tid; i < 64 * 40; i += 256) {
        int r = i / 40, c = i % 40;
        int node = base + r;
        if (node < n) outS[(size_t)node * 40 + c] = lg[r][c] * rsum[r];
    }
}

// ---------------- launch ----------------------------------------------------
extern "C" void kernel_launch(void* const* d_in, const int* in_sizes, int n_in,
                              void* d_out, int out_size) {
    const float* x  = (const float*)d_in[0];
    const void*  ei = d_in[1];
    const float* W1 = (const float*)d_in[2];
    const float* b1 = (const float*)d_in[3];
    const float* W2 = (const float*)d_in[4];
    const float* b2 = (const float*)d_in[5];
    const float* Wc = (const float*)d_in[6];
    const float* bc = (const float*)d_in[7];
    float* out = (float*)d_out;

    int n = in_sizes[0] / INF;   // nodes
    int E = in_sizes[1] / 2;     // edges

    float *ph0, *ph1, *pt, *pemb;
    cudaGetSymbolAddress((void**)&ph0,  g_h0);
    cudaGetSymbolAddress((void**)&ph1,  g_h1);
    cudaGetSymbolAddress((void**)&pt,   g_t);
    cudaGetSymbolAddress((void**)&pemb, g_emb);

    int nb256 = (n + 255) / 256;
    int eb256 = (E + 255) / 256;
    int gBlk  = (n + 127) / 128;
    int fBlk  = (n + 63) / 64;
    int sBlk  = (E + 15) / 16;   // 16 lanes/edge, 16 edges per 256-thread block

    k_detect<<<1, 256>>>((const unsigned int*)ei);
    k_deg_init<<<nb256, 256>>>(n);
    k_deg<<<eb256, 256>>>(ei, E);
    k_dinv<<<nb256, 256>>>(n);

    // conv1: h0 = x@W1 ; h1 init = h0 * dinv^2 (self-loop)
    k_gemm64<INF, false><<<gBlk, 256>>>(x, W1, nullptr, ph0, ph1, n);
    k_scatter<<<sBlk, 256>>>(ei, E, ph0, ph1);

    // conv2: t = relu(h1+b1)@W2 ; emb init = t * dinv^2
    k_gemm64<HID, true><<<gBlk, 256>>>(ph1, W2, b1, pt, pemb, n);
    k_scatter<<<sBlk, 256>>>(ei, E, pt, pemb);

    // head: emb+b2, logits, softmax, argmax
    k_final<<<fBlk, 256>>>(Wc, bc, b2, out, n);
}

// round 5
// speedup vs baseline: 1.8682x; 1.3095x over previous
#include <cuda_runtime.h>
#include <cstdint>
#include <cstdio>

#define NMAX   100000
#define EMAX   1200000
#define INF    128
#define HID    64
#define OUTF   40

// ---------------- scratch (device globals) ---------------------------------
__device__ int   g_degi  [NMAX];        // in-degree (real edges only)
__device__ int   g_start [NMAX];        // CSR row start (by dst)
__device__ int   g_cursor[NMAX];        // placement cursor
__device__ int   g_part  [128];         // scan partials
__device__ int   g_poff  [128];         // scan partial offsets
__device__ float g_dinv  [NMAX];
__device__ int   g_csrc  [EMAX];        // CSR: source node per slot
__device__ float g_cw    [EMAX];        // CSR: edge weight dinv[s]*dinv[d]
__device__ float g_h0    [(size_t)NMAX * HID];   // x @ W1
__device__ float g_h1    [(size_t)NMAX * HID];   // aggregated conv1
__device__ float g_t     [(size_t)NMAX * HID];   // relu(h1+b1) @ W2
__device__ float g_emb   [(size_t)NMAX * HID];   // aggregated conv2
__device__ int   g_idx64;

// ---------------- init: zero degree + dtype sniff --------------------------
__global__ void k_init(const unsigned int* __restrict__ w, int n) {
    int i = blockIdx.x * blockDim.x + threadIdx.x;
    if (i < n) g_degi[i] = 0;
    if (blockIdx.x == 0) {
        int t = threadIdx.x;
        int nz = 0;
#pragma unroll
        for (int k = 0; k < 8; k++) nz |= (w[2 * (t * 8 + k) + 1] != 0u);
        int any = __syncthreads_or(nz);
        if (t == 0) g_idx64 = (any == 0) ? 1 : 0;
    }
}

__device__ __forceinline__ void load_edge(const void* eidx, int E, int e, int& s, int& d) {
    if (g_idx64) {
        const long long* p = (const long long*)eidx;
        s = (int)p[e];
        d = (int)p[(size_t)E + e];
    } else {
        const int* p = (const int*)eidx;
        s = p[e];
        d = p[(size_t)E + e];
    }
}

__global__ void k_deg(const void* __restrict__ eidx, int E) {
    int e = blockIdx.x * blockDim.x + threadIdx.x;
    if (e >= E) return;
    int s, d;
    load_edge(eidx, E, e, s, d);
    atomicAdd(&g_degi[d], 1);
}

// ---------------- 2-level exclusive scan of g_degi -------------------------
// level 1: block (1024 nodes) sums
__global__ void k_scan1(int n) {
    __shared__ int sm[256];
    int t = threadIdx.x;
    int base = blockIdx.x * 1024 + t * 4;
    int s = 0;
#pragma unroll
    for (int j = 0; j < 4; j++) {
        int i = base + j;
        if (i < n) s += g_degi[i];
    }
    sm[t] = s;
    __syncthreads();
    for (int off = 128; off > 0; off >>= 1) {
        if (t < off) sm[t] += sm[t + off];
        __syncthreads();
    }
    if (t == 0) g_part[blockIdx.x] = sm[0];
}

// level 2: exclusive scan of partials (single block)
__global__ void k_scan2(int nblk) {
    __shared__ int sm[128];
    int t = threadIdx.x;
    sm[t] = (t < nblk) ? g_part[t] : 0;
    __syncthreads();
    if (t == 0) {
        int acc = 0;
        for (int i = 0; i < nblk; i++) {
            int v = sm[i];
            sm[i] = acc;
            acc += v;
        }
    }
    __syncthreads();
    if (t < nblk) g_poff[t] = sm[t];
}

// level 3: local exclusive scan + offset; also dinv, cursor
__global__ void k_scan3(int n) {
    __shared__ int sm[256];
    int t = threadIdx.x;
    int base = blockIdx.x * 1024 + t * 4;
    int d[4];
    int s = 0;
#pragma unroll
    for (int j = 0; j < 4; j++) {
        int i = base + j;
        d[j] = (i < n) ? g_degi[i] : 0;
        s += d[j];
    }
    sm[t] = s;
    __syncthreads();
    // Hillis-Steele inclusive scan
    for (int off = 1; off < 256; off <<= 1) {
        int v = (t >= off) ? sm[t - off] : 0;
        __syncthreads();
        sm[t] += v;
        __syncthreads();
    }
    int excl = g_poff[blockIdx.x] + sm[t] - s;
#pragma unroll
    for (int j = 0; j < 4; j++) {
        int i = base + j;
        if (i < n) {
            g_start[i]  = excl;
            g_cursor[i] = excl;
            g_dinv[i]   = rsqrtf((float)d[j] + 1.0f);   // +1 self-loop
        }
        excl += d[j];
    }
}

// ---------------- edge placement into CSR ----------------------------------
__global__ void k_place(const void* __restrict__ eidx, int E) {
    int e = blockIdx.x * blockDim.x + threadIdx.x;
    if (e >= E) return;
    int s, d;
    load_edge(eidx, E, e, s, d);
    int pos = atomicAdd(&g_cursor[d], 1);
    g_csrc[pos] = s;
    g_cw[pos]   = g_dinv[s] * g_dinv[d];
}

// ---------------- GEMM: [n,KDIM] @ [KDIM,64] -> C --------------------------
// BM=128, BN=64, BK=16, 256 threads, 8x4 microtile.
template <int KDIM, bool ACT>
__global__ void k_gemm64(const float* __restrict__ A, const float* __restrict__ W,
                         const float* __restrict__ actb,
                         float* __restrict__ C, int n) {
    __shared__ float xs[16][132];
    __shared__ float ws[16][64];
    const int tid = threadIdx.x;
    const int tx = tid & 15;
    const int ty = tid >> 4;
    const int rowBase = blockIdx.x * 128;

    float acc[8][4];
#pragma unroll
    for (int i = 0; i < 8; i++)
#pragma unroll
        for (int j = 0; j < 4; j++) acc[i][j] = 0.f;

    for (int k0 = 0; k0 < KDIM; k0 += 16) {
#pragma unroll
        for (int half = 0; half < 2; half++) {
            int i  = tid * 4;
            int m  = (i >> 4) + half * 64;
            int kk = i & 15;
            int row = rowBase + m;
            float4 v = make_float4(0.f, 0.f, 0.f, 0.f);
            if (row < n) {
                v = *(const float4*)&A[(size_t)row * KDIM + k0 + kk];
                if (ACT) {
                    v.x = fmaxf(v.x + actb[k0 + kk + 0], 0.f);
                    v.y = fmaxf(v.y + actb[k0 + kk + 1], 0.f);
                    v.z = fmaxf(v.z + actb[k0 + kk + 2], 0.f);
                    v.w = fmaxf(v.w + actb[k0 + kk + 3], 0.f);
                }
            }
            xs[kk + 0][m] = v.x;
            xs[kk + 1][m] = v.y;
            xs[kk + 2][m] = v.z;
            xs[kk + 3][m] = v.w;
        }
        {
            int i  = tid * 4;
            int kk = i >> 6;
            int c  = i & 63;
            *(float4*)&ws[kk][c] = *(const float4*)&W[(size_t)(k0 + kk) * 64 + c];
        }
        __syncthreads();
#pragma unroll
        for (int k = 0; k < 16; k++) {
            float4 b  = *(const float4*)&ws[k][tx * 4];
            float4 a0 = *(const float4*)&xs[k][ty * 8];
            float4 a1 = *(const float4*)&xs[k][ty * 8 + 4];
            float av[8] = {a0.x, a0.y, a0.z, a0.w, a1.x, a1.y, a1.z, a1.w};
            float bv[4] = {b.x, b.y, b.z, b.w};
#pragma unroll
            for (int i = 0; i < 8; i++)
#pragma unroll
                for (int j = 0; j < 4; j++) acc[i][j] += av[i] * bv[j];
        }
        __syncthreads();
    }

#pragma unroll
    for (int i = 0; i < 8; i++) {
        int row = rowBase + ty * 8 + i;
        if (row < n)
            *(float4*)&C[(size_t)row * 64 + tx * 4] =
                make_float4(acc[i][0], acc[i][1], acc[i][2], acc[i][3]);
    }
}

// ---------------- CSR gather aggregation -----------------------------------
// dst[node] = src[node]*dinv[node]^2 + sum_e w_e * src[csrc_e]
// 16 lanes per node (float4 each), 16 nodes per 256-thread block.
__global__ void k_gather(const float* __restrict__ src, float* __restrict__ dst, int n) {
    int node = blockIdx.x * 16 + (threadIdx.x >> 4);
    int lane = threadIdx.x & 15;
    if (node >= n) return;

    const float4* s4 = (const float4*)src;
    float di = g_dinv[node];
    float4 a = s4[(size_t)node * 16 + lane];
    float w0 = di * di;
    float4 acc = make_float4(a.x * w0, a.y * w0, a.z * w0, a.w * w0);

    int e   = g_start[node];
    int end = e + g_degi[node];

    for (; e + 4 <= end; e += 4) {
        int   i0 = g_csrc[e],   i1 = g_csrc[e+1], i2 = g_csrc[e+2], i3 = g_csrc[e+3];
        float w0_ = g_cw[e],    w1_ = g_cw[e+1],  w2_ = g_cw[e+2],  w3_ = g_cw[e+3];
        float4 v0 = s4[(size_t)i0 * 16 + lane];
        float4 v1 = s4[(size_t)i1 * 16 + lane];
        float4 v2 = s4[(size_t)i2 * 16 + lane];
        float4 v3 = s4[(size_t)i3 * 16 + lane];
        acc.x += w0_*v0.x + w1_*v1.x + w2_*v2.x + w3_*v3.x;
        acc.y += w0_*v0.y + w1_*v1.y + w2_*v2.y + w3_*v3.y;
        acc.z += w0_*v0.z + w1_*v1.z + w2_*v2.z + w3_*v3.z;
        acc.w += w0_*v0.w + w1_*v1.w + w2_*v2.w + w3_*v3.w;
    }
    for (; e < end; e++) {
        int   i0 = g_csrc[e];
        float w_ = g_cw[e];
        float4 v0 = s4[(size_t)i0 * 16 + lane];
        acc.x += w_*v0.x; acc.y += w_*v0.y; acc.z += w_*v0.z; acc.w += w_*v0.w;
    }
    ((float4*)dst)[(size_t)node * 16 + lane] = acc;
}

// ---------------- final head: emb+b2, logits, softmax, argmax --------------
__global__ void k_final(const float* __restrict__ Wc, const float* __restrict__ bc,
                        const float* __restrict__ b2,
                        float* __restrict__ out, int n) {
    __shared__ float Wcs[64][40];
    __shared__ float embs[64][65];
    __shared__ float lg[64][41];
    __shared__ float bcs[40];
    __shared__ float b2s[64];
    __shared__ float rsum[64];

    int tid  = threadIdx.x;
    int base = blockIdx.x * 64;

    for (int i = tid; i < 64 * 40; i += 256) Wcs[i / 40][i % 40] = Wc[i];
    if (tid < 40) bcs[tid] = bc[tid];
    if (tid < 64) b2s[tid] = b2[tid];
    __syncthreads();

    float* outL = out;
    float* outE = out + (size_t)n * 40;
    float* outS = out + (size_t)n * 104;
    float* outH = out + (size_t)n * 144;

    for (int i = tid; i < 64 * 64; i += 256) {
        int r = i >> 6, c = i & 63;
        int node = base + r;
        float v = 0.f;
        if (node < n) {
            v = g_emb[(size_t)node * 64 + c] + b2s[c];
            outE[(size_t)node * 64 + c] = v;
        }
        embs[r][c] = v;
    }
    __syncthreads();

    int tx = tid & 7, ty = tid >> 3;
    float acc[2][5];
#pragma unroll
    for (int i = 0; i < 2; i++)
#pragma unroll
        for (int j = 0; j < 5; j++) acc[i][j] = bcs[tx * 5 + j];
    for (int k = 0; k < 64; k++) {
        float a0 = embs[ty * 2 + 0][k];
        float a1 = embs[ty * 2 + 1][k];
#pragma unroll
        for (int j = 0; j < 5; j++) {
            float b = Wcs[k][tx * 5 + j];
            acc[0][j] += a0 * b;
            acc[1][j] += a1 * b;
        }
    }
#pragma unroll
    for (int i = 0; i < 2; i++)
#pragma unroll
        for (int j = 0; j < 5; j++) lg[ty * 2 + i][tx * 5 + j] = acc[i][j];
    __syncthreads();

    for (int i = tid; i < 64 * 40; i += 256) {
        int r = i / 40, c = i % 40;
        int node = base + r;
        if (node < n) outL[(size_t)node * 40 + c] = lg[r][c];
    }
    __syncthreads();

    if (tid < 64) {
        int node = base + tid;
        float m = -1e30f;
        int bi = 0;
#pragma unroll
        for (int j = 0; j < 40; j++) {
            float v = lg[tid][j];
            if (v > m) { m = v; bi = j; }
        }
        float s = 0.f;
#pragma unroll
        for (int j = 0; j < 40; j++) {
            float e = __expf(lg[tid][j] - m);
            lg[tid][j] = e;
            s += e;
        }
        rsum[tid] = 1.f / s;
        if (node < n) outH[node] = (float)bi;
    }
    __syncthreads();

    for (int i = tid; i < 64 * 40; i += 256) {
        int r = i / 40, c = i % 40;
        int node = base + r;
        if (node < n) outS[(size_t)node * 40 + c] = lg[r][c] * rsum[r];
    }
}

// ---------------- launch ----------------------------------------------------
extern "C" void kernel_launch(void* const* d_in, const int* in_sizes, int n_in,
                              void* d_out, int out_size) {
    const float* x  = (const float*)d_in[0];
    const void*  ei = d_in[1];
    const float* W1 = (const float*)d_in[2];
    const float* b1 = (const float*)d_in[3];
    const float* W2 = (const float*)d_in[4];
    const float* b2 = (const float*)d_in[5];
    const float* Wc = (const float*)d_in[6];
    const float* bc = (const float*)d_in[7];
    float* out = (float*)d_out;

    int n = in_sizes[0] / INF;
    int E = in_sizes[1] / 2;

    float *ph0, *ph1, *pt, *pemb;
    cudaGetSymbolAddress((void**)&ph0,  g_h0);
    cudaGetSymbolAddress((void**)&ph1,  g_h1);
    cudaGetSymbolAddress((void**)&pt,   g_t);
    cudaGetSymbolAddress((void**)&pemb, g_emb);

    int nb256 = (n + 255) / 256;
    int eb256 = (E + 255) / 256;
    int sBlk  = (n + 1023) / 1024;
    int gBlk  = (n + 127) / 128;
    int aBlk  = (n + 15) / 16;
    int fBlk  = (n + 63) / 64;

    // CSR build
    k_init <<<nb256, 256>>>((const unsigned int*)ei, n);
    k_deg  <<<eb256, 256>>>(ei, E);
    k_scan1<<<sBlk, 256>>>(n);
    k_scan2<<<1, 128>>>(sBlk);
    k_scan3<<<sBlk, 256>>>(n);
    k_place<<<eb256, 256>>>(ei, E);

    // conv1
    k_gemm64<INF, false><<<gBlk, 256>>>(x, W1, nullptr, ph0, n);
    k_gather<<<aBlk, 256>>>(ph0, ph1, n);

    // conv2
    k_gemm64<HID, true><<<gBlk, 256>>>(ph1, W2, b1, pt, n);
    k_gather<<<aBlk, 256>>>(pt, pemb, n);

    // head
    k_final<<<fBlk, 256>>>(Wc, bc, b2, out, n);
}